// round 1
// baseline (speedup 1.0000x reference)
#include <cuda_runtime.h>

#define BATCH 2
#define CIN 3
#define C2 64
#define H 512
#define W 512
#define MS 504
#define S1 168
#define S2 56
#define S3 19
#define S4 7
#define S5 3

// ---------------- scratch (static device memory; no allocations) ----------------
__device__ unsigned char g_bins[BATCH*CIN*H*W];
__device__ unsigned char g_mode[BATCH*CIN*MS*MS];
__device__ float g_d1[BATCH*C2*S1*S1];
__device__ float g_d2[BATCH*C2*S2*S2];
__device__ float g_d3[BATCH*C2*S3*S3];
__device__ float g_d4[BATCH*C2*S4*S4];
__device__ float g_d5[BATCH*C2*S5*S5];
__device__ float g_bufA[BATCH*C2*H*W];
__device__ float g_bufB[BATCH*C2*H*W];

// ---------------- helpers ----------------
__device__ __forceinline__ float leaky(float x)    { return x >= 0.f ? x : 0.01f*x; }
__device__ __forceinline__ float maxleaky(float x) { return x <= 0.1f ? x : 0.1f + 0.01f*(x - 0.1f); }
__device__ __forceinline__ float minleaky(float x) { return x >= 0.1f ? x : 0.1f + 0.01f*(x - 0.1f); }

// ---------------- 1) quantize to bins ----------------
__global__ void quant_kernel(const float* __restrict__ x) {
    int i = blockIdx.x*blockDim.x + threadIdx.x;
    if (i >= BATCH*CIN*H*W) return;
    // matches round(x*255.0/16.0): x*255 rounds once, /16 is exact
    float t = x[i]*255.0f;
    float r = rintf(t*0.0625f);
    r = fminf(fmaxf(r, 0.f), 16.f);
    g_bins[i] = (unsigned char)r;
}

// ---------------- 2) mode pool 11x11 (pad=1), sliding packed histogram ----------------
__device__ __forceinline__ void hist_add(unsigned long long &h0, unsigned long long &h1, int &h16, int bin) {
    if (bin < 8)       h0 += 1ull << (bin*8);
    else if (bin < 16) h1 += 1ull << ((bin-8)*8);
    else               h16++;
}
__device__ __forceinline__ void hist_sub(unsigned long long &h0, unsigned long long &h1, int &h16, int bin) {
    if (bin < 8)       h0 -= 1ull << (bin*8);
    else if (bin < 16) h1 -= 1ull << ((bin-8)*8);
    else               h16--;
}
__device__ __forceinline__ void row_update(const unsigned char* __restrict__ bp, int yy, int x,
                                           unsigned long long &h0, unsigned long long &h1, int &h16, bool add) {
    if (yy < 0 || yy >= H) { if (add) h0 += 11ull; else h0 -= 11ull; return; }
    const unsigned char* rp = bp + yy*W;
    #pragma unroll
    for (int j = 0; j < 11; j++) {
        int xx = x - 1 + j;
        int bin = (xx >= 0 && xx < W) ? (int)rp[xx] : 0;
        if (add) hist_add(h0, h1, h16, bin); else hist_sub(h0, h1, h16, bin);
    }
}

#define MODE_CHUNK 28
__global__ void mode_kernel() {
    int x = blockIdx.x*blockDim.x + threadIdx.x;
    if (x >= MS) return;
    int bc = blockIdx.z;
    int ystart = blockIdx.y * MODE_CHUNK;
    int yend   = ystart + MODE_CHUNK;   // 18*28 == 504
    const unsigned char* bp = g_bins + (size_t)bc*H*W;
    unsigned char* mp = g_mode + (size_t)bc*MS*MS;

    unsigned long long h0 = 0, h1 = 0; int h16 = 0;
    for (int yy = ystart-1; yy <= ystart+9; yy++) row_update(bp, yy, x, h0, h1, h16, true);

    for (int y = ystart; y < yend; y++) {
        int best = (int)(h0 & 0xffull); int bb = 0;
        #pragma unroll
        for (int bnum = 1; bnum < 8; bnum++) {
            int cn = (int)((h0 >> (bnum*8)) & 0xffull);
            if (cn > best) { best = cn; bb = bnum; }
        }
        #pragma unroll
        for (int bnum = 0; bnum < 8; bnum++) {
            int cn = (int)((h1 >> (bnum*8)) & 0xffull);
            if (cn > best) { best = cn; bb = bnum + 8; }
        }
        if (h16 > best) bb = 16;
        mp[y*MS + x] = (unsigned char)bb;
        if (y + 1 < yend) {
            row_update(bp, y-1,  x, h0, h1, h16, false);
            row_update(bp, y+10, x, h0, h1, h16, true);
        }
    }
}

// ---------------- 3) fused prepare (1x1 convs + clamps) + downgrade level 1 ----------------
__global__ void d1_kernel(const float* __restrict__ w1, const float* __restrict__ b1,
                          const float* __restrict__ w2, const float* __restrict__ b2,
                          const float* __restrict__ dk, const float* __restrict__ dbp) {
    int tile = blockIdx.x;            // 11x11 tiles of 16
    int g = blockIdx.y;               // group 0..31 -> channels 2g, 2g+1
    int b = blockIdx.z;
    int ty = (tile/11)*16 + (threadIdx.x >> 4);
    int tx = (tile%11)*16 + (threadIdx.x & 15);
    if (ty >= S1 || tx >= S1) return;

    int o0 = 2*g, o1 = 2*g + 1;
    float w1a0 = __ldg(w1 + o0*3 + 0), w1a1 = __ldg(w1 + o0*3 + 1), w1a2 = __ldg(w1 + o0*3 + 2);
    float w1b0 = __ldg(w1 + o1*3 + 0), w1b1 = __ldg(w1 + o1*3 + 1), w1b2 = __ldg(w1 + o1*3 + 2);
    float b1a = __ldg(b1 + o0), b1b = __ldg(b1 + o1);
    float w2a0 = __ldg(w2 + o0*2 + 0), w2a1 = __ldg(w2 + o0*2 + 1), b2a = __ldg(b2 + o0);
    float w2b0 = __ldg(w2 + o1*2 + 0), w2b1 = __ldg(w2 + o1*2 + 1), b2b = __ldg(b2 + o1);
    float kk[9];
    #pragma unroll
    for (int i = 0; i < 9; i++) kk[i] = __ldg(dk + i);
    float db = __ldg(dbp);

    const unsigned char* m0 = g_mode + (size_t)(b*CIN + 0)*MS*MS;
    const unsigned char* m1 = g_mode + (size_t)(b*CIN + 1)*MS*MS;
    const unsigned char* m2 = g_mode + (size_t)(b*CIN + 2)*MS*MS;

    float acc0 = db, acc1 = db;
    #pragma unroll
    for (int i = 0; i < 3; i++) {
        #pragma unroll
        for (int j = 0; j < 3; j++) {
            int yy = 3*ty - 1 + i, xx = 3*tx - 1 + j;
            float d0a = 0.f, d0b = 0.f;
            if (yy >= 0 && yy < MS && xx >= 0 && xx < MS) {
                int off = yy*MS + xx;
                float v0 = (float)m0[off]*0.0625f;
                float v1 = (float)m1[off]*0.0625f;
                float v2 = (float)m2[off]*0.0625f;
                float ha = maxleaky(w1a0*v0 + w1a1*v1 + w1a2*v2 + b1a);
                float hb = maxleaky(w1b0*v0 + w1b1*v1 + w1b2*v2 + b1b);
                d0a = minleaky(w2a0*ha + w2a1*hb + b2a);
                d0b = minleaky(w2b0*ha + w2b1*hb + b2b);
            }
            acc0 += kk[i*3+j]*d0a;
            acc1 += kk[i*3+j]*d0b;
        }
    }
    g_d1[((size_t)(b*C2 + o0)*S1 + ty)*S1 + tx] = leaky(acc0);
    g_d1[((size_t)(b*C2 + o1)*S1 + ty)*S1 + tx] = leaky(acc1);
}

// ---------------- 4) downgrade levels 2..5 ----------------
__global__ void down_kernel(int level, const float* __restrict__ dk, const float* __restrict__ dbp) {
    const float* in; float* out; int IS, OS;
    if (level == 2)      { in = g_d1; out = g_d2; IS = S1; OS = S2; }
    else if (level == 3) { in = g_d2; out = g_d3; IS = S2; OS = S3; }
    else if (level == 4) { in = g_d3; out = g_d4; IS = S3; OS = S4; }
    else                 { in = g_d4; out = g_d5; IS = S4; OS = S5; }

    int idx = blockIdx.x*blockDim.x + threadIdx.x;
    int total = BATCH*C2*OS*OS;
    if (idx >= total) return;
    int x = idx % OS;
    int y = (idx/OS) % OS;
    int bc = idx/(OS*OS);
    const float* ip = in + (size_t)bc*IS*IS;
    float acc = __ldg(dbp);
    #pragma unroll
    for (int i = 0; i < 3; i++) {
        #pragma unroll
        for (int j = 0; j < 3; j++) {
            int yy = 3*y - 1 + i, xx = 3*x - 1 + j;
            if (yy >= 0 && yy < IS && xx >= 0 && xx < IS)
                acc += __ldg(dk + i*3 + j) * ip[yy*IS + xx];
        }
    }
    out[idx] = leaky(acc);
}

// ---------------- 5) score: 5 levels of resize -> conv5 -> bn -> leaky, accumulated ----------------
template<int S>
__device__ __forceinline__ void process_level(const float* __restrict__ dch, float* zs,
                                              const float* k5, int y0, int x0, int tid,
                                              int ty, int tx, float iscale, float ibias,
                                              float interpb, float* acc) {
    const float scale = (float)S / 512.0f;
    for (int i = tid; i < 36*36; i += 256) {
        int iu = i / 36;
        int u = y0 - 2 + iu;
        int v = x0 - 2 + (i - iu*36);
        float val = 0.f;
        if ((unsigned)u < (unsigned)H && (unsigned)v < (unsigned)W) {
            float fy = ((float)u + 0.5f)*scale - 0.5f;
            float fx = ((float)v + 0.5f)*scale - 0.5f;
            float fyl = floorf(fy), fxl = floorf(fx);
            float ay = fy - fyl, ax = fx - fxl;
            int y0i = (int)fyl, x0i = (int)fxl;
            int ya = min(max(y0i,     0), S-1);
            int yb = min(max(y0i + 1, 0), S-1);
            int xa = min(max(x0i,     0), S-1);
            int xb = min(max(x0i + 1, 0), S-1);
            float v00 = __ldg(dch + ya*S + xa);
            float v01 = __ldg(dch + ya*S + xb);
            float v10 = __ldg(dch + yb*S + xa);
            float v11 = __ldg(dch + yb*S + xb);
            float top = v00 + ax*(v01 - v00);
            float bot = v10 + ax*(v11 - v10);
            val = top + ay*(bot - top);
        }
        zs[i] = val;
    }
    __syncthreads();
    #pragma unroll
    for (int r = 0; r < 4; r++) {
        int yy = ty + 8*r;
        float t = interpb;
        #pragma unroll
        for (int dy = 0; dy < 5; dy++)
            #pragma unroll
            for (int dx = 0; dx < 5; dx++)
                t += k5[dy*5 + dx] * zs[(yy + dy)*36 + tx + dx];
        t = t*iscale + ibias;
        acc[r] += (t >= 0.f) ? t : 0.01f*t;
    }
    __syncthreads();
}

__global__ void score_kernel(const float* __restrict__ ik, const float* __restrict__ ibp,
                             const float* __restrict__ ig, const float* __restrict__ ibeta,
                             const float* __restrict__ imean, const float* __restrict__ ivar) {
    __shared__ float zs[36*36];
    __shared__ float k5[25];
    int tile = blockIdx.x;            // 16x16 tiles of 32
    int c = blockIdx.y, b = blockIdx.z;
    int y0 = (tile >> 4)*32, x0 = (tile & 15)*32;
    int tid = threadIdx.x;
    if (tid < 25) k5[tid] = __ldg(ik + tid);

    float iscale = __ldg(ig + c) * rsqrtf(__ldg(ivar + c) + 1e-5f);
    float ibias  = __ldg(ibeta + c) - __ldg(imean + c)*iscale;
    float interpb = __ldg(ibp);
    int ty = tid >> 5, tx = tid & 31;
    float acc[4] = {0.f, 0.f, 0.f, 0.f};
    __syncthreads();

    size_t choff;
    choff = (size_t)(b*C2 + c);
    process_level<S1>(g_d1 + choff*S1*S1, zs, k5, y0, x0, tid, ty, tx, iscale, ibias, interpb, acc);
    process_level<S2>(g_d2 + choff*S2*S2, zs, k5, y0, x0, tid, ty, tx, iscale, ibias, interpb, acc);
    process_level<S3>(g_d3 + choff*S3*S3, zs, k5, y0, x0, tid, ty, tx, iscale, ibias, interpb, acc);
    process_level<S4>(g_d4 + choff*S4*S4, zs, k5, y0, x0, tid, ty, tx, iscale, ibias, interpb, acc);
    process_level<S5>(g_d5 + choff*S5*S5, zs, k5, y0, x0, tid, ty, tx, iscale, ibias, interpb, acc);

    float* op = g_bufA + choff*H*W;
    #pragma unroll
    for (int r = 0; r < 4; r++)
        op[(size_t)(y0 + ty + 8*r)*W + x0 + tx] = acc[r];
}

// ---------------- 6) ft: bn + scalar conv + emphase (11x11 unsharp), x3 ----------------
__global__ void ft_kernel(int stage, float* __restrict__ dout,
                          const float* __restrict__ fg, const float* __restrict__ fb,
                          const float* __restrict__ fm, const float* __restrict__ fv,
                          const float* __restrict__ fkp, const float* __restrict__ fbp,
                          const float* __restrict__ ew) {
    __shared__ float ss[42*42];
    __shared__ float hs[42*32];
    int tile = blockIdx.x, c = blockIdx.y, b = blockIdx.z;
    const float* in = (stage == 1) ? g_bufB : g_bufA;
    float* out = (stage == 0) ? g_bufB : ((stage == 1) ? g_bufA : dout);
    int y0 = (tile >> 4)*32, x0 = (tile & 15)*32;

    float sc = __ldg(fg + c) * rsqrtf(__ldg(fv + c) + 1e-5f);
    float k  = __ldg(fkp);
    float A  = sc*k;
    float Bc = (__ldg(fb + c) - __ldg(fm + c)*sc)*k + __ldg(fbp);
    float w  = __ldg(ew + c);

    const float* ip = in + (size_t)(b*C2 + c)*H*W;
    int tid = threadIdx.x;
    for (int i = tid; i < 42*42; i += 256) {
        int iy = i / 42;
        int y = y0 - 5 + iy;
        int x = x0 - 5 + (i - iy*42);
        float v = 0.f;
        if ((unsigned)y < (unsigned)H && (unsigned)x < (unsigned)W)
            v = ip[(size_t)y*W + x]*A + Bc;
        ss[i] = v;
    }
    __syncthreads();
    for (int i = tid; i < 42*32; i += 256) {
        int r = i >> 5, col = i & 31;
        float s = 0.f;
        #pragma unroll
        for (int j = 0; j < 11; j++) s += ss[r*42 + col + j];
        hs[i] = s;
    }
    __syncthreads();
    int ty = tid >> 5, tx = tid & 31;
    float* op = out + (size_t)(b*C2 + c)*H*W;
    #pragma unroll
    for (int r = 0; r < 4; r++) {
        int y = ty + 8*r;
        float box = 0.f;
        #pragma unroll
        for (int j = 0; j < 11; j++) box += hs[(y + j)*32 + tx];
        float scen = ss[(y + 5)*42 + tx + 5];
        float outv = scen + w*(scen - box*(1.0f/121.0f));
        op[(size_t)(y0 + y)*W + x0 + tx] = outv;
    }
}

// ---------------- launch ----------------
extern "C" void kernel_launch(void* const* d_in, const int* in_sizes, int n_in,
                              void* d_out, int out_size) {
    const float* x        = (const float*)d_in[0];
    const float* w1       = (const float*)d_in[1];
    const float* b1       = (const float*)d_in[2];
    const float* w2       = (const float*)d_in[3];
    const float* b2       = (const float*)d_in[4];
    const float* down_k   = (const float*)d_in[5];
    const float* down_b   = (const float*)d_in[6];
    const float* ft_gamma = (const float*)d_in[7];
    const float* ft_beta  = (const float*)d_in[8];
    const float* ft_mean  = (const float*)d_in[9];
    const float* ft_var   = (const float*)d_in[10];
    const float* ft_k     = (const float*)d_in[11];
    const float* ft_b     = (const float*)d_in[12];
    const float* emph_w   = (const float*)d_in[13];
    const float* interp_k = (const float*)d_in[14];
    const float* interp_b = (const float*)d_in[15];
    const float* i_gamma  = (const float*)d_in[16];
    const float* i_beta   = (const float*)d_in[17];
    const float* i_mean   = (const float*)d_in[18];
    const float* i_var    = (const float*)d_in[19];
    float* out = (float*)d_out;

    quant_kernel<<<(BATCH*CIN*H*W + 255)/256, 256>>>(x);

    dim3 mg((MS + 127)/128, MS/MODE_CHUNK, BATCH*CIN);
    mode_kernel<<<mg, 128>>>();

    dim3 g1(121, C2/2, BATCH);
    d1_kernel<<<g1, 256>>>(w1, b1, w2, b2, down_k, down_b);

    down_kernel<<<(BATCH*C2*S2*S2 + 255)/256, 256>>>(2, down_k, down_b);
    down_kernel<<<(BATCH*C2*S3*S3 + 255)/256, 256>>>(3, down_k, down_b);
    down_kernel<<<(BATCH*C2*S4*S4 + 255)/256, 256>>>(4, down_k, down_b);
    down_kernel<<<(BATCH*C2*S5*S5 + 255)/256, 256>>>(5, down_k, down_b);

    dim3 gs(256, C2, BATCH);
    score_kernel<<<gs, 256>>>(interp_k, interp_b, i_gamma, i_beta, i_mean, i_var);

    ft_kernel<<<gs, 256>>>(0, out, ft_gamma, ft_beta, ft_mean, ft_var, ft_k, ft_b, emph_w);
    ft_kernel<<<gs, 256>>>(1, out, ft_gamma, ft_beta, ft_mean, ft_var, ft_k, ft_b, emph_w);
    ft_kernel<<<gs, 256>>>(2, out, ft_gamma, ft_beta, ft_mean, ft_var, ft_k, ft_b, emph_w);
}

// round 2
// speedup vs baseline: 1.2041x; 1.2041x over previous
#include <cuda_runtime.h>

#define BATCH 2
#define CIN 3
#define C2 64
#define H 512
#define W 512
#define MS 504
#define S1 168
#define S2 56
#define S3 19
#define S4 7
#define S5 3

// ---------------- scratch (static device memory; no allocations) ----------------
__device__ unsigned char g_bins[BATCH*CIN*H*W];
__device__ unsigned char g_mode[BATCH*CIN*MS*MS];
__device__ float g_d1[BATCH*C2*S1*S1];
__device__ float g_d2[BATCH*C2*S2*S2];
__device__ float g_d3[BATCH*C2*S3*S3];
__device__ float g_d4[BATCH*C2*S4*S4];
__device__ float g_d5[BATCH*C2*S5*S5];
__device__ float g_bufA[BATCH*C2*H*W];
__device__ float g_bufB[BATCH*C2*H*W];

// ---------------- helpers ----------------
__device__ __forceinline__ float leaky(float x)    { return x >= 0.f ? x : 0.01f*x; }
__device__ __forceinline__ float maxleaky(float x) { return x <= 0.1f ? x : 0.1f + 0.01f*(x - 0.1f); }
__device__ __forceinline__ float minleaky(float x) { return x >= 0.1f ? x : 0.1f + 0.01f*(x - 0.1f); }

// ---------------- 1) quantize to bins (float4 vectorized) ----------------
__global__ void quant_kernel(const float* __restrict__ x) {
    int i = blockIdx.x*blockDim.x + threadIdx.x;
    const int N4 = BATCH*CIN*H*W/4;
    if (i >= N4) return;
    float4 v = ((const float4*)x)[i];
    uchar4 o;
    float r;
    r = fminf(fmaxf(rintf(v.x*255.0f*0.0625f), 0.f), 16.f); o.x = (unsigned char)r;
    r = fminf(fmaxf(rintf(v.y*255.0f*0.0625f), 0.f), 16.f); o.y = (unsigned char)r;
    r = fminf(fmaxf(rintf(v.z*255.0f*0.0625f), 0.f), 16.f); o.z = (unsigned char)r;
    r = fminf(fmaxf(rintf(v.w*255.0f*0.0625f), 0.f), 16.f); o.w = (unsigned char)r;
    ((uchar4*)g_bins)[i] = o;
}

// ---------------- 2) mode pool 11x11 (pad=1), sliding packed histogram ----------------
__device__ __forceinline__ void hist_add(unsigned long long &h0, unsigned long long &h1, int &h16, int bin) {
    if (bin < 8)       h0 += 1ull << (bin*8);
    else if (bin < 16) h1 += 1ull << ((bin-8)*8);
    else               h16++;
}
__device__ __forceinline__ void hist_sub(unsigned long long &h0, unsigned long long &h1, int &h16, int bin) {
    if (bin < 8)       h0 -= 1ull << (bin*8);
    else if (bin < 16) h1 -= 1ull << ((bin-8)*8);
    else               h16--;
}
template<bool INTERIOR>
__device__ __forceinline__ void row_update(const unsigned char* __restrict__ bp, int yy, int x,
                                           unsigned long long &h0, unsigned long long &h1, int &h16, bool add) {
    if (yy < 0 || yy >= H) { if (add) h0 += 11ull; else h0 -= 11ull; return; }
    const unsigned char* rp = bp + yy*W;
    #pragma unroll
    for (int j = 0; j < 11; j++) {
        int xx = x - 1 + j;
        int bin;
        if (INTERIOR) bin = (int)rp[xx];
        else          bin = (xx >= 0 && xx < W) ? (int)rp[xx] : 0;
        if (add) hist_add(h0, h1, h16, bin); else hist_sub(h0, h1, h16, bin);
    }
}

#define MODE_CHUNK 14
template<bool INTERIOR>
__device__ __forceinline__ void mode_body(int x, int bc, int ystart) {
    int yend = ystart + MODE_CHUNK;
    const unsigned char* bp = g_bins + (size_t)bc*H*W;
    unsigned char* mp = g_mode + (size_t)bc*MS*MS;

    unsigned long long h0 = 0, h1 = 0; int h16 = 0;
    for (int yy = ystart-1; yy <= ystart+9; yy++) row_update<INTERIOR>(bp, yy, x, h0, h1, h16, true);

    for (int y = ystart; y < yend; y++) {
        int best = (int)(h0 & 0xffull); int bb = 0;
        #pragma unroll
        for (int bnum = 1; bnum < 8; bnum++) {
            int cn = (int)((h0 >> (bnum*8)) & 0xffull);
            if (cn > best) { best = cn; bb = bnum; }
        }
        #pragma unroll
        for (int bnum = 0; bnum < 8; bnum++) {
            int cn = (int)((h1 >> (bnum*8)) & 0xffull);
            if (cn > best) { best = cn; bb = bnum + 8; }
        }
        if (h16 > best) bb = 16;
        mp[y*MS + x] = (unsigned char)bb;
        if (y + 1 < yend) {
            row_update<INTERIOR>(bp, y-1,  x, h0, h1, h16, false);
            row_update<INTERIOR>(bp, y+10, x, h0, h1, h16, true);
        }
    }
}

__global__ void mode_kernel() {
    int x = blockIdx.x*blockDim.x + threadIdx.x;
    if (x >= MS) return;
    int bc = blockIdx.z;
    int ystart = blockIdx.y * MODE_CHUNK;
    // xx = x-1+j spans [x-1, x+9]; only x==0 (xx=-1) or x==503 (xx=512) go out of bounds
    if (x >= 1 && x <= 502) mode_body<true>(x, bc, ystart);
    else                    mode_body<false>(x, bc, ystart);
}

// ---------------- 3) fused prepare (1x1 convs + clamps) + downgrade level 1 ----------------
__global__ void d1_kernel(const float* __restrict__ w1, const float* __restrict__ b1,
                          const float* __restrict__ w2, const float* __restrict__ b2,
                          const float* __restrict__ dk, const float* __restrict__ dbp) {
    int tile = blockIdx.x;            // 11x11 tiles of 16
    int g = blockIdx.y;               // group 0..31 -> channels 2g, 2g+1
    int b = blockIdx.z;
    int ty = (tile/11)*16 + (threadIdx.x >> 4);
    int tx = (tile%11)*16 + (threadIdx.x & 15);
    if (ty >= S1 || tx >= S1) return;

    int o0 = 2*g, o1 = 2*g + 1;
    float w1a0 = __ldg(w1 + o0*3 + 0), w1a1 = __ldg(w1 + o0*3 + 1), w1a2 = __ldg(w1 + o0*3 + 2);
    float w1b0 = __ldg(w1 + o1*3 + 0), w1b1 = __ldg(w1 + o1*3 + 1), w1b2 = __ldg(w1 + o1*3 + 2);
    float b1a = __ldg(b1 + o0), b1b = __ldg(b1 + o1);
    float w2a0 = __ldg(w2 + o0*2 + 0), w2a1 = __ldg(w2 + o0*2 + 1), b2a = __ldg(b2 + o0);
    float w2b0 = __ldg(w2 + o1*2 + 0), w2b1 = __ldg(w2 + o1*2 + 1), b2b = __ldg(b2 + o1);
    float kk[9];
    #pragma unroll
    for (int i = 0; i < 9; i++) kk[i] = __ldg(dk + i);
    float db = __ldg(dbp);

    const unsigned char* m0 = g_mode + (size_t)(b*CIN + 0)*MS*MS;
    const unsigned char* m1 = g_mode + (size_t)(b*CIN + 1)*MS*MS;
    const unsigned char* m2 = g_mode + (size_t)(b*CIN + 2)*MS*MS;

    float acc0 = db, acc1 = db;
    #pragma unroll
    for (int i = 0; i < 3; i++) {
        #pragma unroll
        for (int j = 0; j < 3; j++) {
            int yy = 3*ty - 1 + i, xx = 3*tx - 1 + j;
            float d0a = 0.f, d0b = 0.f;
            if (yy >= 0 && yy < MS && xx >= 0 && xx < MS) {
                int off = yy*MS + xx;
                float v0 = (float)m0[off]*0.0625f;
                float v1 = (float)m1[off]*0.0625f;
                float v2 = (float)m2[off]*0.0625f;
                float ha = maxleaky(w1a0*v0 + w1a1*v1 + w1a2*v2 + b1a);
                float hb = maxleaky(w1b0*v0 + w1b1*v1 + w1b2*v2 + b1b);
                d0a = minleaky(w2a0*ha + w2a1*hb + b2a);
                d0b = minleaky(w2b0*ha + w2b1*hb + b2b);
            }
            acc0 += kk[i*3+j]*d0a;
            acc1 += kk[i*3+j]*d0b;
        }
    }
    g_d1[((size_t)(b*C2 + o0)*S1 + ty)*S1 + tx] = leaky(acc0);
    g_d1[((size_t)(b*C2 + o1)*S1 + ty)*S1 + tx] = leaky(acc1);
}

// ---------------- 4) downgrade level 2 (56x56, needs parallelism) ----------------
__global__ void down2_kernel(const float* __restrict__ dk, const float* __restrict__ dbp) {
    int idx = blockIdx.x*blockDim.x + threadIdx.x;
    const int total = BATCH*C2*S2*S2;
    if (idx >= total) return;
    int x = idx % S2;
    int y = (idx/S2) % S2;
    int bc = idx/(S2*S2);
    const float* ip = g_d1 + (size_t)bc*S1*S1;
    float acc = __ldg(dbp);
    #pragma unroll
    for (int i = 0; i < 3; i++) {
        #pragma unroll
        for (int j = 0; j < 3; j++) {
            int yy = 3*y - 1 + i, xx = 3*x - 1 + j;
            if (yy >= 0 && yy < S1 && xx >= 0 && xx < S1)
                acc += __ldg(dk + i*3 + j) * ip[yy*S1 + xx];
        }
    }
    g_d2[idx] = leaky(acc);
}

// ---------------- 4b) downgrade levels 3,4,5 fused (per-(b,c) block, serial levels) ----------------
template<int IS, int OS>
__device__ __forceinline__ void down_step(const float* __restrict__ in, float* __restrict__ out,
                                          const float* kk, float db, int tid, int nthr) {
    for (int i = tid; i < OS*OS; i += nthr) {
        int x = i % OS, y = i / OS;
        float acc = db;
        #pragma unroll
        for (int ii = 0; ii < 3; ii++) {
            #pragma unroll
            for (int jj = 0; jj < 3; jj++) {
                int yy = 3*y - 1 + ii, xx = 3*x - 1 + jj;
                if (yy >= 0 && yy < IS && xx >= 0 && xx < IS)
                    acc += kk[ii*3+jj] * in[yy*IS + xx];
            }
        }
        out[i] = leaky(acc);
    }
}

__global__ void down345_kernel(const float* __restrict__ dk, const float* __restrict__ dbp) {
    int bc = blockIdx.x;  // 0..127
    int tid = threadIdx.x;
    float kk[9];
    #pragma unroll
    for (int i = 0; i < 9; i++) kk[i] = __ldg(dk + i);
    float db = __ldg(dbp);
    down_step<S2, S3>(g_d2 + (size_t)bc*S2*S2, g_d3 + (size_t)bc*S3*S3, kk, db, tid, blockDim.x);
    __syncthreads();
    down_step<S3, S4>(g_d3 + (size_t)bc*S3*S3, g_d4 + (size_t)bc*S4*S4, kk, db, tid, blockDim.x);
    __syncthreads();
    down_step<S4, S5>(g_d4 + (size_t)bc*S4*S4, g_d5 + (size_t)bc*S5*S5, kk, db, tid, blockDim.x);
}

// ---------------- 5) score: 5 levels of resize -> conv5 -> bn -> leaky, accumulated ----------------
// Tile 64 wide x 32 tall, 256 threads. Thread: 4 contiguous rows x 2 cols.
#define ZS_STRIDE 72

struct ScoreShared {
    float zs[36*ZS_STRIDE];
    float k5[25];
    int   ro0[36]; int ro1[36]; float rw[36]; float rv[36];
    int   co0[68]; int co1[68]; float cw[68]; float cv[68];
};

template<int S>
__device__ __forceinline__ void score_level(ScoreShared* sh, const float* __restrict__ dch,
                                            int ty0, int tx0, int tid,
                                            float iscale, float ibias, float interpb,
                                            float sacc[4][2]) {
    const float scale = (float)S / 512.0f;
    // row params
    if (tid < 36) {
        int u = ty0 - 2 + tid;
        float fy = ((float)u + 0.5f)*scale - 0.5f;
        float fyl = floorf(fy);
        int y0i = (int)fyl;
        int ya = min(max(y0i,     0), S-1);
        int yb = min(max(y0i + 1, 0), S-1);
        sh->ro0[tid] = ya*S;
        sh->ro1[tid] = yb*S;
        sh->rw[tid]  = fy - fyl;
        sh->rv[tid]  = ((unsigned)u < (unsigned)H) ? 1.0f : 0.0f;
    } else if (tid >= 64 && tid < 132) {
        int cc = tid - 64;
        int v = tx0 - 2 + cc;
        float fx = ((float)v + 0.5f)*scale - 0.5f;
        float fxl = floorf(fx);
        int x0i = (int)fxl;
        int xa = min(max(x0i,     0), S-1);
        int xb = min(max(x0i + 1, 0), S-1);
        sh->co0[cc] = xa;
        sh->co1[cc] = xb;
        sh->cw[cc]  = fx - fxl;
        sh->cv[cc]  = ((unsigned)v < (unsigned)W) ? 1.0f : 0.0f;
    }
    __syncthreads();
    // bilinear fill: 36 x 68
    for (int i = tid; i < 36*68; i += 256) {
        int iu = i / 68;
        int iv = i - iu*68;
        int r0 = sh->ro0[iu], r1 = sh->ro1[iu];
        int c0 = sh->co0[iv], c1 = sh->co1[iv];
        float ay = sh->rw[iu], ax = sh->cw[iv];
        float m = sh->rv[iu] * sh->cv[iv];
        float v00 = __ldg(dch + r0 + c0);
        float v01 = __ldg(dch + r0 + c1);
        float v10 = __ldg(dch + r1 + c0);
        float v11 = __ldg(dch + r1 + c1);
        float top = v00 + ax*(v01 - v00);
        float bot = v10 + ax*(v11 - v10);
        sh->zs[iu*ZS_STRIDE + iv] = m*(top + ay*(bot - top));
    }
    __syncthreads();
    // conv 5x5: thread g=tid>>5 rows 4g..4g+3, p=tid&31 cols 2p,2p+1
    int g = tid >> 5;
    int p = tid & 31;
    float a[4][2] = {{0.f,0.f},{0.f,0.f},{0.f,0.f},{0.f,0.f}};
    #pragma unroll
    for (int iy = 0; iy < 8; iy++) {
        const float* rp = &sh->zs[(4*g + iy)*ZS_STRIDE + 2*p];
        float2 u0 = *(const float2*)(rp);
        float2 u1 = *(const float2*)(rp + 2);
        float2 u2 = *(const float2*)(rp + 4);
        float v0 = u0.x, v1 = u0.y, v2 = u1.x, v3 = u1.y, v4 = u2.x, v5 = u2.y;
        #pragma unroll
        for (int r = 0; r < 4; r++) {
            int dy = iy - r;
            if (dy >= 0 && dy <= 4) {
                const float* kr = &sh->k5[dy*5];
                a[r][0] += kr[0]*v0 + kr[1]*v1 + kr[2]*v2 + kr[3]*v3 + kr[4]*v4;
                a[r][1] += kr[0]*v1 + kr[1]*v2 + kr[2]*v3 + kr[3]*v4 + kr[4]*v5;
            }
        }
    }
    #pragma unroll
    for (int r = 0; r < 4; r++) {
        #pragma unroll
        for (int cc = 0; cc < 2; cc++) {
            float t = (a[r][cc] + interpb)*iscale + ibias;
            sacc[r][cc] += (t >= 0.f) ? t : 0.01f*t;
        }
    }
    __syncthreads();
}

__global__ void __launch_bounds__(256) score_kernel(
                             const float* __restrict__ ik, const float* __restrict__ ibp,
                             const float* __restrict__ ig, const float* __restrict__ ibeta,
                             const float* __restrict__ imean, const float* __restrict__ ivar) {
    __shared__ ScoreShared sh;
    int tile = blockIdx.x;            // 8 x-tiles x 16 y-tiles
    int c = blockIdx.y, b = blockIdx.z;
    int tx0 = (tile & 7)*64, ty0 = (tile >> 3)*32;
    int tid = threadIdx.x;
    if (tid < 25) sh.k5[tid] = __ldg(ik + tid);

    float iscale = __ldg(ig + c) * rsqrtf(__ldg(ivar + c) + 1e-5f);
    float ibias  = __ldg(ibeta + c) - __ldg(imean + c)*iscale;
    float interpb = __ldg(ibp);
    float sacc[4][2] = {{0.f,0.f},{0.f,0.f},{0.f,0.f},{0.f,0.f}};

    size_t choff = (size_t)(b*C2 + c);
    score_level<S1>(&sh, g_d1 + choff*S1*S1, ty0, tx0, tid, iscale, ibias, interpb, sacc);
    score_level<S2>(&sh, g_d2 + choff*S2*S2, ty0, tx0, tid, iscale, ibias, interpb, sacc);
    score_level<S3>(&sh, g_d3 + choff*S3*S3, ty0, tx0, tid, iscale, ibias, interpb, sacc);
    score_level<S4>(&sh, g_d4 + choff*S4*S4, ty0, tx0, tid, iscale, ibias, interpb, sacc);
    score_level<S5>(&sh, g_d5 + choff*S5*S5, ty0, tx0, tid, iscale, ibias, interpb, sacc);

    int g = tid >> 5, p = tid & 31;
    float* op = g_bufA + choff*H*W;
    #pragma unroll
    for (int r = 0; r < 4; r++) {
        float2 o2; o2.x = sacc[r][0]; o2.y = sacc[r][1];
        *(float2*)(op + (size_t)(ty0 + 4*g + r)*W + tx0 + 2*p) = o2;
    }
}

// ---------------- 6) ft: bn + scalar conv + emphase (11x11 unsharp), x3 ----------------
#define SS_STRIDE 45
#define HS_STRIDE 33
__global__ void __launch_bounds__(256) ft_kernel(int stage, float* __restrict__ dout,
                          const float* __restrict__ fg, const float* __restrict__ fb,
                          const float* __restrict__ fm, const float* __restrict__ fv,
                          const float* __restrict__ fkp, const float* __restrict__ fbp,
                          const float* __restrict__ ew) {
    __shared__ float ss[42*SS_STRIDE];
    __shared__ float hs[42*HS_STRIDE];
    int tile = blockIdx.x, c = blockIdx.y, b = blockIdx.z;
    const float* in = (stage == 1) ? g_bufB : g_bufA;
    float* out = (stage == 0) ? g_bufB : ((stage == 1) ? g_bufA : dout);
    int y0 = (tile >> 4)*32, x0 = (tile & 15)*32;

    float sc = __ldg(fg + c) * rsqrtf(__ldg(fv + c) + 1e-5f);
    float k  = __ldg(fkp);
    float A  = sc*k;
    float Bc = (__ldg(fb + c) - __ldg(fm + c)*sc)*k + __ldg(fbp);
    float w  = __ldg(ew + c);
    float wc1 = 1.0f + w;
    float wc2 = w*(1.0f/121.0f);

    const float* ip = in + (size_t)(b*C2 + c)*H*W;
    int tid = threadIdx.x;
    // fill 42x42 (affine applied; zero outside image)
    for (int i = tid; i < 42*42; i += 256) {
        int iy = i / 42;
        int ix = i - iy*42;
        int y = y0 - 5 + iy;
        int x = x0 - 5 + ix;
        float v = 0.f;
        if ((unsigned)y < (unsigned)H && (unsigned)x < (unsigned)W)
            v = ip[(size_t)y*W + x]*A + Bc;
        ss[iy*SS_STRIDE + ix] = v;
    }
    __syncthreads();
    // horizontal 11-sum, incremental: 42 rows x 8 groups of 4 cols
    for (int t = tid; t < 42*8; t += 256) {
        int r = t >> 3;
        int cg = (t & 7)*4;
        const float* base = &ss[r*SS_STRIDE + cg];
        float s0 = 0.f;
        #pragma unroll
        for (int j = 0; j < 11; j++) s0 += base[j];
        float s1 = s0 + base[11] - base[0];
        float s2 = s1 + base[12] - base[1];
        float s3 = s2 + base[13] - base[2];
        float* hp = &hs[r*HS_STRIDE + cg];
        hp[0] = s0; hp[1] = s1; hp[2] = s2; hp[3] = s3;
    }
    __syncthreads();
    // vertical 11-sum incremental + emphase: thread = col (tid&31) x rowgroup (tid>>5)
    int cc = tid & 31;
    int g = tid >> 5;
    int yb = 4*g;
    float v0 = 0.f;
    #pragma unroll
    for (int j = 0; j < 11; j++) v0 += hs[(yb + j)*HS_STRIDE + cc];
    float v1 = v0 + hs[(yb+11)*HS_STRIDE + cc] - hs[(yb+0)*HS_STRIDE + cc];
    float v2 = v1 + hs[(yb+12)*HS_STRIDE + cc] - hs[(yb+1)*HS_STRIDE + cc];
    float v3 = v2 + hs[(yb+13)*HS_STRIDE + cc] - hs[(yb+2)*HS_STRIDE + cc];
    float box[4] = {v0, v1, v2, v3};
    float* op = out + (size_t)(b*C2 + c)*H*W;
    #pragma unroll
    for (int r = 0; r < 4; r++) {
        int y = yb + r;
        float scen = ss[(y + 5)*SS_STRIDE + cc + 5];
        op[(size_t)(y0 + y)*W + x0 + cc] = scen*wc1 - wc2*box[r];
    }
}

// ---------------- launch ----------------
extern "C" void kernel_launch(void* const* d_in, const int* in_sizes, int n_in,
                              void* d_out, int out_size) {
    const float* x        = (const float*)d_in[0];
    const float* w1       = (const float*)d_in[1];
    const float* b1       = (const float*)d_in[2];
    const float* w2       = (const float*)d_in[3];
    const float* b2       = (const float*)d_in[4];
    const float* down_k   = (const float*)d_in[5];
    const float* down_b   = (const float*)d_in[6];
    const float* ft_gamma = (const float*)d_in[7];
    const float* ft_beta  = (const float*)d_in[8];
    const float* ft_mean  = (const float*)d_in[9];
    const float* ft_var   = (const float*)d_in[10];
    const float* ft_k     = (const float*)d_in[11];
    const float* ft_b     = (const float*)d_in[12];
    const float* emph_w   = (const float*)d_in[13];
    const float* interp_k = (const float*)d_in[14];
    const float* interp_b = (const float*)d_in[15];
    const float* i_gamma  = (const float*)d_in[16];
    const float* i_beta   = (const float*)d_in[17];
    const float* i_mean   = (const float*)d_in[18];
    const float* i_var    = (const float*)d_in[19];
    float* out = (float*)d_out;

    quant_kernel<<<(BATCH*CIN*H*W/4 + 255)/256, 256>>>(x);                 // launch 0

    dim3 mg((MS + 127)/128, MS/MODE_CHUNK, BATCH*CIN);
    mode_kernel<<<mg, 128>>>();                                            // launch 1

    dim3 g1(121, C2/2, BATCH);
    d1_kernel<<<g1, 256>>>(w1, b1, w2, b2, down_k, down_b);                // launch 2

    down2_kernel<<<(BATCH*C2*S2*S2 + 255)/256, 256>>>(down_k, down_b);     // launch 3
    down345_kernel<<<BATCH*C2, 384>>>(down_k, down_b);                     // launch 4

    dim3 gs(128, C2, BATCH);
    score_kernel<<<gs, 256>>>(interp_k, interp_b, i_gamma, i_beta, i_mean, i_var); // launch 5 (ncu)

    dim3 gf(256, C2, BATCH);
    ft_kernel<<<gf, 256>>>(0, out, ft_gamma, ft_beta, ft_mean, ft_var, ft_k, ft_b, emph_w);
    ft_kernel<<<gf, 256>>>(1, out, ft_gamma, ft_beta, ft_mean, ft_var, ft_k, ft_b, emph_w);
    ft_kernel<<<gf, 256>>>(2, out, ft_gamma, ft_beta, ft_mean, ft_var, ft_k, ft_b, emph_w);
}